// round 7
// baseline (speedup 1.0000x reference)
#include <cuda_runtime.h>
#include <math.h>

#define B_   8
#define C_   256
#define K_   4
#define H_   128
#define W_   128
#define HW_  (H_*W_)
#define NPIX (B_*HW_)

// Scratch (static device globals; no allocation in kernel_launch)
__device__ float g_proj[33554432];   // [b][p][c] channels-last, 134 MB
__device__ float g_feat[33554432];   // [gp][c] channels-last (BN-scaled), 134 MB
__device__ float g_off[(size_t)NPIX * 12]; // per pixel: 8 flow (k-major x,y) + 4 logits
__device__ float g_convwT[C_*C_];    // [c][o]
__device__ float g_outwT[C_*C_];     // [c][o]
__device__ float g_inv[C_];
__device__ float g_shift[C_];
__device__ float g_bias2[C_];

// ---------------------------------------------------------------------------
// K0: fold BN into scale/shift, pre-transpose weights, fold shift into out bias
// ---------------------------------------------------------------------------
__global__ void prep_kernel(const float* __restrict__ conv_w,
                            const float* __restrict__ out_w,
                            const float* __restrict__ gamma,
                            const float* __restrict__ beta,
                            const float* __restrict__ rmean,
                            const float* __restrict__ rvar,
                            const float* __restrict__ out_b) {
    int t = threadIdx.x;
    float inv = gamma[t] / sqrtf(rvar[t] + 1e-5f);
    g_inv[t]   = inv;
    g_shift[t] = beta[t] - inv * rmean[t];
    for (int i = t; i < C_*C_; i += 256) {
        int o = i >> 8, c = i & 255;
        g_convwT[c*C_ + o] = conv_w[i];
        g_outwT [c*C_ + o] = out_w[i];
    }
    __syncthreads();
    float s = out_b[t];
    #pragma unroll 4
    for (int c = 0; c < C_; c++) s += out_w[t*C_ + c] * g_shift[c];
    g_bias2[t] = s;
}

// ---------------------------------------------------------------------------
// K1: proj GEMM  proj[b][p][o] = sum_c x[b][c][p] * conv_w[o][c] + conv_b[o]
// 128x128 tile, BK=8, 256 threads, 8x8 microtile. tx -> pixel dim, ty -> out dim
// ---------------------------------------------------------------------------
__global__ void __launch_bounds__(256,2)
gemm_proj(const float* __restrict__ x, const float* __restrict__ conv_b) {
    __shared__ float As[8][128];
    __shared__ float Bs[8][128];
    int b  = blockIdx.z;
    int p0 = blockIdx.x * 128;
    int o0 = blockIdx.y * 128;
    const float* xb = x + (size_t)b * C_ * HW_;
    int tid = threadIdx.x;
    int tx = tid & 15, ty = tid >> 4;

    float acc[8][8];
    #pragma unroll
    for (int i = 0; i < 8; i++)
        #pragma unroll
        for (int j = 0; j < 8; j++) acc[i][j] = 0.f;

    for (int c0 = 0; c0 < C_; c0 += 8) {
        #pragma unroll
        for (int i = 0; i < 4; i++) {
            int idx = tid + i*256;
            int kc = idx >> 7, col = idx & 127;
            As[kc][col] = xb[(size_t)(c0+kc)*HW_ + p0 + col];
            Bs[kc][col] = g_convwT[(c0+kc)*C_ + o0 + col];
        }
        __syncthreads();
        #pragma unroll
        for (int kc = 0; kc < 8; kc++) {
            float a[8], bb[8];
            *(float4*)&a[0]  = *(const float4*)&As[kc][tx*8];
            *(float4*)&a[4]  = *(const float4*)&As[kc][tx*8+4];
            *(float4*)&bb[0] = *(const float4*)&Bs[kc][ty*8];
            *(float4*)&bb[4] = *(const float4*)&Bs[kc][ty*8+4];
            #pragma unroll
            for (int i = 0; i < 8; i++)
                #pragma unroll
                for (int j = 0; j < 8; j++)
                    acc[i][j] += a[i]*bb[j];
        }
        __syncthreads();
    }

    float bias[8];
    #pragma unroll
    for (int j = 0; j < 8; j++) bias[j] = conv_b[o0 + ty*8 + j];
    #pragma unroll
    for (int i = 0; i < 8; i++) {
        int p = p0 + tx*8 + i;
        float* dst = &g_proj[((size_t)b*HW_ + p)*C_ + o0 + ty*8];
        float4 v0 = make_float4(acc[i][0]+bias[0], acc[i][1]+bias[1],
                                acc[i][2]+bias[2], acc[i][3]+bias[3]);
        float4 v1 = make_float4(acc[i][4]+bias[4], acc[i][5]+bias[5],
                                acc[i][6]+bias[6], acc[i][7]+bias[7]);
        *(float4*)dst     = v0;
        *(float4*)(dst+4) = v1;
    }
}

// ---------------------------------------------------------------------------
// K2: flows (8) + logits (4) per pixel. 256 threads x 4 pixels each.
// ---------------------------------------------------------------------------
__global__ void off_kernel(const float* __restrict__ x,
                           const float* __restrict__ off_w,
                           const float* __restrict__ off_b,
                           const float* __restrict__ wgt_w,
                           const float* __restrict__ wgt_b) {
    __shared__ float sw[C_*12]; // sw[c*12 + j]
    int tid = threadIdx.x;
    for (int i = tid; i < C_*12; i += 256) {
        int c = i / 12, j = i % 12;
        sw[i] = (j < 8) ? off_w[j*C_ + c] : wgt_w[(j-8)*C_ + c];
    }
    __syncthreads();

    int gp0 = (blockIdx.x*256 + tid) * 4;
    int b = gp0 >> 14;
    int p = gp0 & (HW_-1);
    const float* xb = x + (size_t)b * C_ * HW_ + p;

    float acc[12][4];
    #pragma unroll
    for (int j = 0; j < 12; j++)
        acc[j][0] = acc[j][1] = acc[j][2] = acc[j][3] = 0.f;

    for (int c = 0; c < C_; c++) {
        float4 xv = *(const float4*)(xb + (size_t)c*HW_);
        const float* w = &sw[c*12];
        #pragma unroll
        for (int j = 0; j < 12; j++) {
            float wj = w[j];
            acc[j][0] += wj*xv.x; acc[j][1] += wj*xv.y;
            acc[j][2] += wj*xv.z; acc[j][3] += wj*xv.w;
        }
    }
    #pragma unroll
    for (int q = 0; q < 4; q++) {
        float* dst = &g_off[(size_t)(gp0+q)*12];
        #pragma unroll
        for (int j = 0; j < 12; j++)
            dst[j] = acc[j][q] + ((j < 8) ? off_b[j] : wgt_b[j-8]);
    }
}

// ---------------------------------------------------------------------------
// K3: softmax over k, bilinear gather of proj (channels-last), BN scale fold.
// 64 threads (float4 each) per pixel; 4 pixels per 256-thread block.
// ---------------------------------------------------------------------------
__global__ void sample_kernel() {
    int tid  = threadIdx.x;
    int g    = tid >> 6;
    int lane = tid & 63;
    int gp = blockIdx.x*4 + g;
    int b  = gp >> 14;
    int p  = gp & (HW_-1);
    int py = p >> 7, px = p & 127;

    const float4* offv = (const float4*)(&g_off[(size_t)gp*12]);
    float4 o0 = offv[0], o1 = offv[1], o2 = offv[2];
    float fxs[4] = {o0.x, o0.z, o1.x, o1.z};
    float fys[4] = {o0.y, o0.w, o1.y, o1.w};
    float lg[4]  = {o2.x, o2.y, o2.z, o2.w};

    float m = fmaxf(fmaxf(lg[0],lg[1]), fmaxf(lg[2],lg[3]));
    float e[4]; float es = 0.f;
    #pragma unroll
    for (int k = 0; k < 4; k++) { e[k] = expf(lg[k]-m); es += e[k]; }
    float einv = 1.f/es;

    float coef[16];
    int   ridx[16];
    #pragma unroll
    for (int k = 0; k < 4; k++) {
        float wk = e[k]*einv;
        float vx = (float)px + fxs[k];
        float vy = (float)py + fys[k];
        // replicate ref's normalize->unnormalize exactly (align_corners=True)
        float gxn = 2.f*vx/127.f - 1.f;
        float gyn = 2.f*vy/127.f - 1.f;
        float xx = (gxn + 1.f)*0.5f*127.f;
        float yy = (gyn + 1.f)*0.5f*127.f;
        float x0 = floorf(xx), y0 = floorf(yy);
        float wx1 = xx - x0, wy1 = yy - y0;
        float cw[4]  = {(1.f-wx1)*(1.f-wy1), wx1*(1.f-wy1), (1.f-wx1)*wy1, wx1*wy1};
        float cxs[4] = {x0, x0+1.f, x0,     x0+1.f};
        float cys[4] = {y0, y0,     y0+1.f, y0+1.f};
        #pragma unroll
        for (int t = 0; t < 4; t++) {
            bool valid = (cxs[t] >= 0.f) && (cxs[t] <= 127.f)
                      && (cys[t] >= 0.f) && (cys[t] <= 127.f);
            int xi = (int)fminf(fmaxf(cxs[t], 0.f), 127.f);
            int yi = (int)fminf(fmaxf(cys[t], 0.f), 127.f);
            coef[k*4+t] = valid ? wk*cw[t] : 0.f;
            ridx[k*4+t] = yi*128 + xi;
        }
    }

    const float4* projb = (const float4*)g_proj + (size_t)b*HW_*64;
    float4 acc = projb[(size_t)p*64 + lane]; // feat = proj + fsum
    #pragma unroll
    for (int t = 0; t < 16; t++) {
        float cf = coef[t];
        if (cf != 0.f) {
            float4 v = projb[(size_t)ridx[t]*64 + lane];
            acc.x += cf*v.x; acc.y += cf*v.y; acc.z += cf*v.z; acc.w += cf*v.w;
        }
    }
    float4 iv = ((const float4*)g_inv)[lane];
    float4 fo;
    fo.x = iv.x*acc.x; fo.y = iv.y*acc.y; fo.z = iv.z*acc.z; fo.w = iv.w*acc.w;
    ((float4*)g_feat)[(size_t)gp*64 + lane] = fo;
}

// ---------------------------------------------------------------------------
// K4: out GEMM  out[b][o][p] = sum_c feat[gp][c] * out_w[o][c] + bias2[o]
// pixels across lanes -> fully coalesced float4 stores into [B,C,H,W] output.
// ---------------------------------------------------------------------------
__global__ void __launch_bounds__(256,2)
gemm_out(float* __restrict__ out) {
    __shared__ float As[8][128];
    __shared__ float Bs[8][128];
    int gp0 = blockIdx.x * 128;
    int o0  = blockIdx.y * 128;
    int b   = gp0 >> 14;
    int p0  = gp0 & (HW_-1);
    int tid = threadIdx.x;
    int tx = tid & 15, ty = tid >> 4;
    int ppL = tid >> 1;
    int kq  = (tid & 1) * 4;

    float acc[8][8];
    #pragma unroll
    for (int i = 0; i < 8; i++)
        #pragma unroll
        for (int j = 0; j < 8; j++) acc[i][j] = 0.f;

    for (int c0 = 0; c0 < C_; c0 += 8) {
        float4 av = *(const float4*)(&g_feat[((size_t)(gp0+ppL))*C_ + c0 + kq]);
        As[kq+0][ppL] = av.x; As[kq+1][ppL] = av.y;
        As[kq+2][ppL] = av.z; As[kq+3][ppL] = av.w;
        #pragma unroll
        for (int i = 0; i < 4; i++) {
            int idx = tid + i*256;
            int kc = idx >> 7, col = idx & 127;
            Bs[kc][col] = g_outwT[(c0+kc)*C_ + o0 + col];
        }
        __syncthreads();
        #pragma unroll
        for (int kc = 0; kc < 8; kc++) {
            float a[8], bb[8];
            *(float4*)&a[0]  = *(const float4*)&As[kc][tx*8];
            *(float4*)&a[4]  = *(const float4*)&As[kc][tx*8+4];
            *(float4*)&bb[0] = *(const float4*)&Bs[kc][ty*8];
            *(float4*)&bb[4] = *(const float4*)&Bs[kc][ty*8+4];
            #pragma unroll
            for (int i = 0; i < 8; i++)
                #pragma unroll
                for (int j = 0; j < 8; j++)
                    acc[i][j] += a[i]*bb[j];
        }
        __syncthreads();
    }

    #pragma unroll
    for (int j = 0; j < 8; j++) {
        int o = o0 + ty*8 + j;
        float bz = g_bias2[o];
        float* dst = out + ((size_t)b*C_ + o)*HW_ + p0 + tx*8;
        float4 v0 = make_float4(acc[0][j]+bz, acc[1][j]+bz, acc[2][j]+bz, acc[3][j]+bz);
        float4 v1 = make_float4(acc[4][j]+bz, acc[5][j]+bz, acc[6][j]+bz, acc[7][j]+bz);
        *(float4*)dst     = v0;
        *(float4*)(dst+4) = v1;
    }
}

// ---------------------------------------------------------------------------
extern "C" void kernel_launch(void* const* d_in, const int* in_sizes, int n_in,
                              void* d_out, int out_size) {
    const float* x      = (const float*)d_in[0];
    const float* conv_w = (const float*)d_in[1];
    const float* conv_b = (const float*)d_in[2];
    const float* off_w  = (const float*)d_in[3];
    const float* off_b  = (const float*)d_in[4];
    const float* wgt_w  = (const float*)d_in[5];
    const float* wgt_b  = (const float*)d_in[6];
    const float* gamma  = (const float*)d_in[7];
    const float* beta   = (const float*)d_in[8];
    const float* rmean  = (const float*)d_in[9];
    const float* rvar   = (const float*)d_in[10];
    const float* out_w  = (const float*)d_in[11];
    const float* out_b  = (const float*)d_in[12];
    float* out = (float*)d_out;

    prep_kernel<<<1, 256>>>(conv_w, out_w, gamma, beta, rmean, rvar, out_b);
    off_kernel<<<NPIX/1024, 256>>>(x, off_w, off_b, wgt_w, wgt_b);
    dim3 g1(HW_/128, C_/128, B_);
    gemm_proj<<<g1, 256>>>(x, conv_b);
    sample_kernel<<<NPIX/4, 256>>>();
    dim3 g2(NPIX/128, C_/128);
    gemm_out<<<g2, 256>>>(out);
}

// round 8
// speedup vs baseline: 1.0014x; 1.0014x over previous
#include <cuda_runtime.h>
#include <math.h>

#define B_   8
#define C_   256
#define K_   4
#define H_   128
#define W_   128
#define HW_  (H_*W_)
#define NPIX (B_*HW_)

// Scratch (static device globals; no allocation in kernel_launch)
__device__ float g_proj[33554432];   // [b][p][c] channels-last, 134 MB
__device__ float g_feat[33554432];   // [gp][c] channels-last (BN-scaled), 134 MB
__device__ float g_off[(size_t)NPIX * 12]; // per pixel: 8 flow (k-major x,y) + 4 logits
__device__ float g_convwT[C_*C_];    // [c][o]
__device__ float g_outwT[C_*C_];     // [c][o]
__device__ float g_inv[C_];
__device__ float g_shift[C_];
__device__ float g_bias2[C_];

// ---------------------------------------------------------------------------
// K0: fold BN into scale/shift, pre-transpose weights, fold shift into out bias
// ---------------------------------------------------------------------------
__global__ void prep_kernel(const float* __restrict__ conv_w,
                            const float* __restrict__ out_w,
                            const float* __restrict__ gamma,
                            const float* __restrict__ beta,
                            const float* __restrict__ rmean,
                            const float* __restrict__ rvar,
                            const float* __restrict__ out_b) {
    int t = threadIdx.x;
    float inv = gamma[t] / sqrtf(rvar[t] + 1e-5f);
    g_inv[t]   = inv;
    g_shift[t] = beta[t] - inv * rmean[t];
    for (int i = t; i < C_*C_; i += 256) {
        int o = i >> 8, c = i & 255;
        g_convwT[c*C_ + o] = conv_w[i];
        g_outwT [c*C_ + o] = out_w[i];
    }
    __syncthreads();
    float s = out_b[t];
    #pragma unroll 4
    for (int c = 0; c < C_; c++) s += out_w[t*C_ + c] * g_shift[c];
    g_bias2[t] = s;
}

// ---------------------------------------------------------------------------
// K1: proj GEMM  proj[b][p][o] = sum_c x[b][c][p] * conv_w[o][c] + conv_b[o]
// 128x128 tile, BK=8, 256 threads, 8x8 microtile. tx -> pixel dim, ty -> out dim
// ---------------------------------------------------------------------------
__global__ void __launch_bounds__(256,2)
gemm_proj(const float* __restrict__ x, const float* __restrict__ conv_b) {
    __shared__ float As[8][128];
    __shared__ float Bs[8][128];
    int b  = blockIdx.z;
    int p0 = blockIdx.x * 128;
    int o0 = blockIdx.y * 128;
    const float* xb = x + (size_t)b * C_ * HW_;
    int tid = threadIdx.x;
    int tx = tid & 15, ty = tid >> 4;

    float acc[8][8];
    #pragma unroll
    for (int i = 0; i < 8; i++)
        #pragma unroll
        for (int j = 0; j < 8; j++) acc[i][j] = 0.f;

    for (int c0 = 0; c0 < C_; c0 += 8) {
        #pragma unroll
        for (int i = 0; i < 4; i++) {
            int idx = tid + i*256;
            int kc = idx >> 7, col = idx & 127;
            As[kc][col] = xb[(size_t)(c0+kc)*HW_ + p0 + col];
            Bs[kc][col] = g_convwT[(c0+kc)*C_ + o0 + col];
        }
        __syncthreads();
        #pragma unroll
        for (int kc = 0; kc < 8; kc++) {
            float a[8], bb[8];
            *(float4*)&a[0]  = *(const float4*)&As[kc][tx*8];
            *(float4*)&a[4]  = *(const float4*)&As[kc][tx*8+4];
            *(float4*)&bb[0] = *(const float4*)&Bs[kc][ty*8];
            *(float4*)&bb[4] = *(const float4*)&Bs[kc][ty*8+4];
            #pragma unroll
            for (int i = 0; i < 8; i++)
                #pragma unroll
                for (int j = 0; j < 8; j++)
                    acc[i][j] += a[i]*bb[j];
        }
        __syncthreads();
    }

    float bias[8];
    #pragma unroll
    for (int j = 0; j < 8; j++) bias[j] = conv_b[o0 + ty*8 + j];
    #pragma unroll
    for (int i = 0; i < 8; i++) {
        int p = p0 + tx*8 + i;
        float* dst = &g_proj[((size_t)b*HW_ + p)*C_ + o0 + ty*8];
        float4 v0 = make_float4(acc[i][0]+bias[0], acc[i][1]+bias[1],
                                acc[i][2]+bias[2], acc[i][3]+bias[3]);
        float4 v1 = make_float4(acc[i][4]+bias[4], acc[i][5]+bias[5],
                                acc[i][6]+bias[6], acc[i][7]+bias[7]);
        *(float4*)dst     = v0;
        *(float4*)(dst+4) = v1;
    }
}

// ---------------------------------------------------------------------------
// K2: flows (8) + logits (4) per pixel. 256 threads x 4 pixels each.
// ---------------------------------------------------------------------------
__global__ void off_kernel(const float* __restrict__ x,
                           const float* __restrict__ off_w,
                           const float* __restrict__ off_b,
                           const float* __restrict__ wgt_w,
                           const float* __restrict__ wgt_b) {
    __shared__ float sw[C_*12]; // sw[c*12 + j]
    int tid = threadIdx.x;
    for (int i = tid; i < C_*12; i += 256) {
        int c = i / 12, j = i % 12;
        sw[i] = (j < 8) ? off_w[j*C_ + c] : wgt_w[(j-8)*C_ + c];
    }
    __syncthreads();

    int gp0 = (blockIdx.x*256 + tid) * 4;
    int b = gp0 >> 14;
    int p = gp0 & (HW_-1);
    const float* xb = x + (size_t)b * C_ * HW_ + p;

    float acc[12][4];
    #pragma unroll
    for (int j = 0; j < 12; j++)
        acc[j][0] = acc[j][1] = acc[j][2] = acc[j][3] = 0.f;

    for (int c = 0; c < C_; c++) {
        float4 xv = *(const float4*)(xb + (size_t)c*HW_);
        const float* w = &sw[c*12];
        #pragma unroll
        for (int j = 0; j < 12; j++) {
            float wj = w[j];
            acc[j][0] += wj*xv.x; acc[j][1] += wj*xv.y;
            acc[j][2] += wj*xv.z; acc[j][3] += wj*xv.w;
        }
    }
    #pragma unroll
    for (int q = 0; q < 4; q++) {
        float* dst = &g_off[(size_t)(gp0+q)*12];
        #pragma unroll
        for (int j = 0; j < 12; j++)
            dst[j] = acc[j][q] + ((j < 8) ? off_b[j] : wgt_b[j-8]);
    }
}

// ---------------------------------------------------------------------------
// K3: softmax over k, bilinear gather of proj (channels-last), BN scale fold.
// 64 threads (float4 each) per pixel; 4 pixels per 256-thread block.
// ---------------------------------------------------------------------------
__global__ void sample_kernel() {
    int tid  = threadIdx.x;
    int g    = tid >> 6;
    int lane = tid & 63;
    int gp = blockIdx.x*4 + g;
    int b  = gp >> 14;
    int p  = gp & (HW_-1);
    int py = p >> 7, px = p & 127;

    const float4* offv = (const float4*)(&g_off[(size_t)gp*12]);
    float4 o0 = offv[0], o1 = offv[1], o2 = offv[2];
    float fxs[4] = {o0.x, o0.z, o1.x, o1.z};
    float fys[4] = {o0.y, o0.w, o1.y, o1.w};
    float lg[4]  = {o2.x, o2.y, o2.z, o2.w};

    float m = fmaxf(fmaxf(lg[0],lg[1]), fmaxf(lg[2],lg[3]));
    float e[4]; float es = 0.f;
    #pragma unroll
    for (int k = 0; k < 4; k++) { e[k] = expf(lg[k]-m); es += e[k]; }
    float einv = 1.f/es;

    float coef[16];
    int   ridx[16];
    #pragma unroll
    for (int k = 0; k < 4; k++) {
        float wk = e[k]*einv;
        float vx = (float)px + fxs[k];
        float vy = (float)py + fys[k];
        // replicate ref's normalize->unnormalize exactly (align_corners=True)
        float gxn = 2.f*vx/127.f - 1.f;
        float gyn = 2.f*vy/127.f - 1.f;
        float xx = (gxn + 1.f)*0.5f*127.f;
        float yy = (gyn + 1.f)*0.5f*127.f;
        float x0 = floorf(xx), y0 = floorf(yy);
        float wx1 = xx - x0, wy1 = yy - y0;
        float cw[4]  = {(1.f-wx1)*(1.f-wy1), wx1*(1.f-wy1), (1.f-wx1)*wy1, wx1*wy1};
        float cxs[4] = {x0, x0+1.f, x0,     x0+1.f};
        float cys[4] = {y0, y0,     y0+1.f, y0+1.f};
        #pragma unroll
        for (int t = 0; t < 4; t++) {
            bool valid = (cxs[t] >= 0.f) && (cxs[t] <= 127.f)
                      && (cys[t] >= 0.f) && (cys[t] <= 127.f);
            int xi = (int)fminf(fmaxf(cxs[t], 0.f), 127.f);
            int yi = (int)fminf(fmaxf(cys[t], 0.f), 127.f);
            coef[k*4+t] = valid ? wk*cw[t] : 0.f;
            ridx[k*4+t] = yi*128 + xi;
        }
    }

    const float4* projb = (const float4*)g_proj + (size_t)b*HW_*64;
    float4 acc = projb[(size_t)p*64 + lane]; // feat = proj + fsum
    #pragma unroll
    for (int t = 0; t < 16; t++) {
        float cf = coef[t];
        if (cf != 0.f) {
            float4 v = projb[(size_t)ridx[t]*64 + lane];
            acc.x += cf*v.x; acc.y += cf*v.y; acc.z += cf*v.z; acc.w += cf*v.w;
        }
    }
    float4 iv = ((const float4*)g_inv)[lane];
    float4 fo;
    fo.x = iv.x*acc.x; fo.y = iv.y*acc.y; fo.z = iv.z*acc.z; fo.w = iv.w*acc.w;
    ((float4*)g_feat)[(size_t)gp*64 + lane] = fo;
}

// ---------------------------------------------------------------------------
// K4: out GEMM  out[b][o][p] = sum_c feat[gp][c] * out_w[o][c] + bias2[o]
// pixels across lanes -> fully coalesced float4 stores into [B,C,H,W] output.
// ---------------------------------------------------------------------------
__global__ void __launch_bounds__(256,2)
gemm_out(float* __restrict__ out) {
    __shared__ float As[8][128];
    __shared__ float Bs[8][128];
    int gp0 = blockIdx.x * 128;
    int o0  = blockIdx.y * 128;
    int b   = gp0 >> 14;
    int p0  = gp0 & (HW_-1);
    int tid = threadIdx.x;
    int tx = tid & 15, ty = tid >> 4;
    int ppL = tid >> 1;
    int kq  = (tid & 1) * 4;

    float acc[8][8];
    #pragma unroll
    for (int i = 0; i < 8; i++)
        #pragma unroll
        for (int j = 0; j < 8; j++) acc[i][j] = 0.f;

    for (int c0 = 0; c0 < C_; c0 += 8) {
        float4 av = *(const float4*)(&g_feat[((size_t)(gp0+ppL))*C_ + c0 + kq]);
        As[kq+0][ppL] = av.x; As[kq+1][ppL] = av.y;
        As[kq+2][ppL] = av.z; As[kq+3][ppL] = av.w;
        #pragma unroll
        for (int i = 0; i < 4; i++) {
            int idx = tid + i*256;
            int kc = idx >> 7, col = idx & 127;
            Bs[kc][col] = g_outwT[(c0+kc)*C_ + o0 + col];
        }
        __syncthreads();
        #pragma unroll
        for (int kc = 0; kc < 8; kc++) {
            float a[8], bb[8];
            *(float4*)&a[0]  = *(const float4*)&As[kc][tx*8];
            *(float4*)&a[4]  = *(const float4*)&As[kc][tx*8+4];
            *(float4*)&bb[0] = *(const float4*)&Bs[kc][ty*8];
            *(float4*)&bb[4] = *(const float4*)&Bs[kc][ty*8+4];
            #pragma unroll
            for (int i = 0; i < 8; i++)
                #pragma unroll
                for (int j = 0; j < 8; j++)
                    acc[i][j] += a[i]*bb[j];
        }
        __syncthreads();
    }

    #pragma unroll
    for (int j = 0; j < 8; j++) {
        int o = o0 + ty*8 + j;
        float bz = g_bias2[o];
        float* dst = out + ((size_t)b*C_ + o)*HW_ + p0 + tx*8;
        float4 v0 = make_float4(acc[0][j]+bz, acc[1][j]+bz, acc[2][j]+bz, acc[3][j]+bz);
        float4 v1 = make_float4(acc[4][j]+bz, acc[5][j]+bz, acc[6][j]+bz, acc[7][j]+bz);
        *(float4*)dst     = v0;
        *(float4*)(dst+4) = v1;
    }
}

// ---------------------------------------------------------------------------
extern "C" void kernel_launch(void* const* d_in, const int* in_sizes, int n_in,
                              void* d_out, int out_size) {
    const float* x      = (const float*)d_in[0];
    const float* conv_w = (const float*)d_in[1];
    const float* conv_b = (const float*)d_in[2];
    const float* off_w  = (const float*)d_in[3];
    const float* off_b  = (const float*)d_in[4];
    const float* wgt_w  = (const float*)d_in[5];
    const float* wgt_b  = (const float*)d_in[6];
    const float* gamma  = (const float*)d_in[7];
    const float* beta   = (const float*)d_in[8];
    const float* rmean  = (const float*)d_in[9];
    const float* rvar   = (const float*)d_in[10];
    const float* out_w  = (const float*)d_in[11];
    const float* out_b  = (const float*)d_in[12];
    float* out = (float*)d_out;

    prep_kernel<<<1, 256>>>(conv_w, out_w, gamma, beta, rmean, rvar, out_b);
    off_kernel<<<NPIX/1024, 256>>>(x, off_w, off_b, wgt_w, wgt_b);
    dim3 g1(HW_/128, C_/128, B_);
    gemm_proj<<<g1, 256>>>(x, conv_b);
    sample_kernel<<<NPIX/4, 256>>>();
    dim3 g2(NPIX/128, C_/128);
    gemm_out<<<g2, 256>>>(out);
}

// round 13
// speedup vs baseline: 1.0038x; 1.0024x over previous
#include <cuda_runtime.h>
#include <math.h>

#define B_   8
#define C_   256
#define K_   4
#define H_   128
#define W_   128
#define HW_  (H_*W_)
#define NPIX (B_*HW_)

// Scratch (static device globals; no allocation in kernel_launch)
__device__ float g_proj[33554432];   // [b][p][c] channels-last, 134 MB
__device__ float g_feat[33554432];   // [gp][c] channels-last (BN-scaled), 134 MB
__device__ float g_off[(size_t)NPIX * 12]; // per pixel: 8 flow (k-major x,y) + 4 logits
__device__ float g_convwT[C_*C_];    // [c][o]
__device__ float g_outwT[C_*C_];     // [c][o]
__device__ float g_inv[C_];
__device__ float g_shift[C_];
__device__ float g_bias2[C_];

// ---------------------------------------------------------------------------
// K0: fold BN into scale/shift, pre-transpose weights, fold shift into out bias
// ---------------------------------------------------------------------------
__global__ void prep_kernel(const float* __restrict__ conv_w,
                            const float* __restrict__ out_w,
                            const float* __restrict__ gamma,
                            const float* __restrict__ beta,
                            const float* __restrict__ rmean,
                            const float* __restrict__ rvar,
                            const float* __restrict__ out_b) {
    int t = threadIdx.x;
    float inv = gamma[t] / sqrtf(rvar[t] + 1e-5f);
    g_inv[t]   = inv;
    g_shift[t] = beta[t] - inv * rmean[t];
    for (int i = t; i < C_*C_; i += 256) {
        int o = i >> 8, c = i & 255;
        g_convwT[c*C_ + o] = conv_w[i];
        g_outwT [c*C_ + o] = out_w[i];
    }
    __syncthreads();
    float s = out_b[t];
    #pragma unroll 4
    for (int c = 0; c < C_; c++) s += out_w[t*C_ + c] * g_shift[c];
    g_bias2[t] = s;
}

// ---------------------------------------------------------------------------
// K1: proj GEMM  proj[b][p][o] = sum_c x[b][c][p] * conv_w[o][c] + conv_b[o]
// 128x128 tile, BK=8, 256 threads, 8x8 microtile. tx -> pixel dim, ty -> out dim
// ---------------------------------------------------------------------------
__global__ void __launch_bounds__(256,2)
gemm_proj(const float* __restrict__ x, const float* __restrict__ conv_b) {
    __shared__ float As[8][128];
    __shared__ float Bs[8][128];
    int b  = blockIdx.z;
    int p0 = blockIdx.x * 128;
    int o0 = blockIdx.y * 128;
    const float* xb = x + (size_t)b * C_ * HW_;
    int tid = threadIdx.x;
    int tx = tid & 15, ty = tid >> 4;

    float acc[8][8];
    #pragma unroll
    for (int i = 0; i < 8; i++)
        #pragma unroll
        for (int j = 0; j < 8; j++) acc[i][j] = 0.f;

    for (int c0 = 0; c0 < C_; c0 += 8) {
        #pragma unroll
        for (int i = 0; i < 4; i++) {
            int idx = tid + i*256;
            int kc = idx >> 7, col = idx & 127;
            As[kc][col] = xb[(size_t)(c0+kc)*HW_ + p0 + col];
            Bs[kc][col] = g_convwT[(c0+kc)*C_ + o0 + col];
        }
        __syncthreads();
        #pragma unroll
        for (int kc = 0; kc < 8; kc++) {
            float a[8], bb[8];
            *(float4*)&a[0]  = *(const float4*)&As[kc][tx*8];
            *(float4*)&a[4]  = *(const float4*)&As[kc][tx*8+4];
            *(float4*)&bb[0] = *(const float4*)&Bs[kc][ty*8];
            *(float4*)&bb[4] = *(const float4*)&Bs[kc][ty*8+4];
            #pragma unroll
            for (int i = 0; i < 8; i++)
                #pragma unroll
                for (int j = 0; j < 8; j++)
                    acc[i][j] += a[i]*bb[j];
        }
        __syncthreads();
    }

    float bias[8];
    #pragma unroll
    for (int j = 0; j < 8; j++) bias[j] = conv_b[o0 + ty*8 + j];
    #pragma unroll
    for (int i = 0; i < 8; i++) {
        int p = p0 + tx*8 + i;
        float* dst = &g_proj[((size_t)b*HW_ + p)*C_ + o0 + ty*8];
        float4 v0 = make_float4(acc[i][0]+bias[0], acc[i][1]+bias[1],
                                acc[i][2]+bias[2], acc[i][3]+bias[3]);
        float4 v1 = make_float4(acc[i][4]+bias[4], acc[i][5]+bias[5],
                                acc[i][6]+bias[6], acc[i][7]+bias[7]);
        *(float4*)dst     = v0;
        *(float4*)(dst+4) = v1;
    }
}

// ---------------------------------------------------------------------------
// K2: flows (8) + logits (4) per pixel. 256 threads x 4 pixels each.
// ---------------------------------------------------------------------------
__global__ void off_kernel(const float* __restrict__ x,
                           const float* __restrict__ off_w,
                           const float* __restrict__ off_b,
                           const float* __restrict__ wgt_w,
                           const float* __restrict__ wgt_b) {
    __shared__ float sw[C_*12]; // sw[c*12 + j]
    int tid = threadIdx.x;
    for (int i = tid; i < C_*12; i += 256) {
        int c = i / 12, j = i % 12;
        sw[i] = (j < 8) ? off_w[j*C_ + c] : wgt_w[(j-8)*C_ + c];
    }
    __syncthreads();

    int gp0 = (blockIdx.x*256 + tid) * 4;
    int b = gp0 >> 14;
    int p = gp0 & (HW_-1);
    const float* xb = x + (size_t)b * C_ * HW_ + p;

    float acc[12][4];
    #pragma unroll
    for (int j = 0; j < 12; j++)
        acc[j][0] = acc[j][1] = acc[j][2] = acc[j][3] = 0.f;

    for (int c = 0; c < C_; c++) {
        float4 xv = *(const float4*)(xb + (size_t)c*HW_);
        const float* w = &sw[c*12];
        #pragma unroll
        for (int j = 0; j < 12; j++) {
            float wj = w[j];
            acc[j][0] += wj*xv.x; acc[j][1] += wj*xv.y;
            acc[j][2] += wj*xv.z; acc[j][3] += wj*xv.w;
        }
    }
    #pragma unroll
    for (int q = 0; q < 4; q++) {
        float* dst = &g_off[(size_t)(gp0+q)*12];
        #pragma unroll
        for (int j = 0; j < 12; j++)
            dst[j] = acc[j][q] + ((j < 8) ? off_b[j] : wgt_b[j-8]);
    }
}

// ---------------------------------------------------------------------------
// K3: softmax over k, bilinear gather of proj (channels-last), BN scale fold.
// 64 threads (float4 each) per pixel; 4 pixels per 256-thread block.
// ---------------------------------------------------------------------------
__global__ void sample_kernel() {
    int tid  = threadIdx.x;
    int g    = tid >> 6;
    int lane = tid & 63;
    int gp = blockIdx.x*4 + g;
    int b  = gp >> 14;
    int p  = gp & (HW_-1);
    int py = p >> 7, px = p & 127;

    const float4* offv = (const float4*)(&g_off[(size_t)gp*12]);
    float4 o0 = offv[0], o1 = offv[1], o2 = offv[2];
    float fxs[4] = {o0.x, o0.z, o1.x, o1.z};
    float fys[4] = {o0.y, o0.w, o1.y, o1.w};
    float lg[4]  = {o2.x, o2.y, o2.z, o2.w};

    float m = fmaxf(fmaxf(lg[0],lg[1]), fmaxf(lg[2],lg[3]));
    float e[4]; float es = 0.f;
    #pragma unroll
    for (int k = 0; k < 4; k++) { e[k] = expf(lg[k]-m); es += e[k]; }
    float einv = 1.f/es;

    float coef[16];
    int   ridx[16];
    #pragma unroll
    for (int k = 0; k < 4; k++) {
        float wk = e[k]*einv;
        float vx = (float)px + fxs[k];
        float vy = (float)py + fys[k];
        // replicate ref's normalize->unnormalize exactly (align_corners=True)
        float gxn = 2.f*vx/127.f - 1.f;
        float gyn = 2.f*vy/127.f - 1.f;
        float xx = (gxn + 1.f)*0.5f*127.f;
        float yy = (gyn + 1.f)*0.5f*127.f;
        float x0 = floorf(xx), y0 = floorf(yy);
        float wx1 = xx - x0, wy1 = yy - y0;
        float cw[4]  = {(1.f-wx1)*(1.f-wy1), wx1*(1.f-wy1), (1.f-wx1)*wy1, wx1*wy1};
        float cxs[4] = {x0, x0+1.f, x0,     x0+1.f};
        float cys[4] = {y0, y0,     y0+1.f, y0+1.f};
        #pragma unroll
        for (int t = 0; t < 4; t++) {
            bool valid = (cxs[t] >= 0.f) && (cxs[t] <= 127.f)
                      && (cys[t] >= 0.f) && (cys[t] <= 127.f);
            int xi = (int)fminf(fmaxf(cxs[t], 0.f), 127.f);
            int yi = (int)fminf(fmaxf(cys[t], 0.f), 127.f);
            coef[k*4+t] = valid ? wk*cw[t] : 0.f;
            ridx[k*4+t] = yi*128 + xi;
        }
    }

    const float4* projb = (const float4*)g_proj + (size_t)b*HW_*64;
    float4 acc = projb[(size_t)p*64 + lane]; // feat = proj + fsum
    #pragma unroll
    for (int t = 0; t < 16; t++) {
        float cf = coef[t];
        if (cf != 0.f) {
            float4 v = projb[(size_t)ridx[t]*64 + lane];
            acc.x += cf*v.x; acc.y += cf*v.y; acc.z += cf*v.z; acc.w += cf*v.w;
        }
    }
    float4 iv = ((const float4*)g_inv)[lane];
    float4 fo;
    fo.x = iv.x*acc.x; fo.y = iv.y*acc.y; fo.z = iv.z*acc.z; fo.w = iv.w*acc.w;
    ((float4*)g_feat)[(size_t)gp*64 + lane] = fo;
}

// ---------------------------------------------------------------------------
// K4: out GEMM  out[b][o][p] = sum_c feat[gp][c] * out_w[o][c] + bias2[o]
// pixels across lanes -> fully coalesced float4 stores into [B,C,H,W] output.
// ---------------------------------------------------------------------------
__global__ void __launch_bounds__(256,2)
gemm_out(float* __restrict__ out) {
    __shared__ float As[8][128];
    __shared__ float Bs[8][128];
    int gp0 = blockIdx.x * 128;
    int o0  = blockIdx.y * 128;
    int b   = gp0 >> 14;
    int p0  = gp0 & (HW_-1);
    int tid = threadIdx.x;
    int tx = tid & 15, ty = tid >> 4;
    int ppL = tid >> 1;
    int kq  = (tid & 1) * 4;

    float acc[8][8];
    #pragma unroll
    for (int i = 0; i < 8; i++)
        #pragma unroll
        for (int j = 0; j < 8; j++) acc[i][j] = 0.f;

    for (int c0 = 0; c0 < C_; c0 += 8) {
        float4 av = *(const float4*)(&g_feat[((size_t)(gp0+ppL))*C_ + c0 + kq]);
        As[kq+0][ppL] = av.x; As[kq+1][ppL] = av.y;
        As[kq+2][ppL] = av.z; As[kq+3][ppL] = av.w;
        #pragma unroll
        for (int i = 0; i < 4; i++) {
            int idx = tid + i*256;
            int kc = idx >> 7, col = idx & 127;
            Bs[kc][col] = g_outwT[(c0+kc)*C_ + o0 + col];
        }
        __syncthreads();
        #pragma unroll
        for (int kc = 0; kc < 8; kc++) {
            float a[8], bb[8];
            *(float4*)&a[0]  = *(const float4*)&As[kc][tx*8];
            *(float4*)&a[4]  = *(const float4*)&As[kc][tx*8+4];
            *(float4*)&bb[0] = *(const float4*)&Bs[kc][ty*8];
            *(float4*)&bb[4] = *(const float4*)&Bs[kc][ty*8+4];
            #pragma unroll
            for (int i = 0; i < 8; i++)
                #pragma unroll
                for (int j = 0; j < 8; j++)
                    acc[i][j] += a[i]*bb[j];
        }
        __syncthreads();
    }

    #pragma unroll
    for (int j = 0; j < 8; j++) {
        int o = o0 + ty*8 + j;
        float bz = g_bias2[o];
        float* dst = out + ((size_t)b*C_ + o)*HW_ + p0 + tx*8;
        float4 v0 = make_float4(acc[0][j]+bz, acc[1][j]+bz, acc[2][j]+bz, acc[3][j]+bz);
        float4 v1 = make_float4(acc[4][j]+bz, acc[5][j]+bz, acc[6][j]+bz, acc[7][j]+bz);
        *(float4*)dst     = v0;
        *(float4*)(dst+4) = v1;
    }
}

// ---------------------------------------------------------------------------
extern "C" void kernel_launch(void* const* d_in, const int* in_sizes, int n_in,
                              void* d_out, int out_size) {
    const float* x      = (const float*)d_in[0];
    const float* conv_w = (const float*)d_in[1];
    const float* conv_b = (const float*)d_in[2];
    const float* off_w  = (const float*)d_in[3];
    const float* off_b  = (const float*)d_in[4];
    const float* wgt_w  = (const float*)d_in[5];
    const float* wgt_b  = (const float*)d_in[6];
    const float* gamma  = (const float*)d_in[7];
    const float* beta   = (const float*)d_in[8];
    const float* rmean  = (const float*)d_in[9];
    const float* rvar   = (const float*)d_in[10];
    const float* out_w  = (const float*)d_in[11];
    const float* out_b  = (const float*)d_in[12];
    float* out = (float*)d_out;

    prep_kernel<<<1, 256>>>(conv_w, out_w, gamma, beta, rmean, rvar, out_b);
    off_kernel<<<NPIX/1024, 256>>>(x, off_w, off_b, wgt_w, wgt_b);
    dim3 g1(HW_/128, C_/128, B_);
    gemm_proj<<<g1, 256>>>(x, conv_b);
    sample_kernel<<<NPIX/4, 256>>>();
    dim3 g2(NPIX/128, C_/128);
    gemm_out<<<g2, 256>>>(out);
}